// round 14
// baseline (speedup 1.0000x reference)
#include <cuda_runtime.h>

// Problem dims (fixed)
#define BB   512
#define TT   100
#define II   700
#define HH   128
#define OO   20
#define NROWS (BB*TT)
#define MW   24                    // padded mask words per row (22 used + 2 zero)
#define CHUNK_I 192                // i-rows per weight chunk
#define CHUNK_W 6                  // mask words per chunk
#define NCHUNK 4
#define GW_ROWS 11                 // rows per warp in single-pass gather
#define TRANS_BLOCKS 350           // CTAs of fused kernel doing the transpose

#define ALPHA 0.81873075307798182f // exp(-0.2)
#define BETA  0.90483741803595957f // exp(-0.1)
#define LAM   0.95122942450071400f // exp(-0.05)

// Device-global scratch (allocation-free)
static __device__ float    g_W0T[II * HH];               // W0^T [i][h]
static __device__ unsigned g_masks[(size_t)NROWS * MW];  // input spike bitmasks (sequential)
static __device__ float    g_U[(size_t)NROWS * HH];      // U = X @ W0^T
static __device__ float    g_G[(size_t)NROWS * HH];      // G = k0 @ W1^T

// ---------------------------------------------------------------------------
// K0 (launch 0): FUSED transpose + input-bitmask extraction (MLP-6 loads,
// sequential bit order: word w bit j <-> element 32w+j).
// ---------------------------------------------------------------------------
__global__ void __launch_bounds__(256) k_fused_tm(const float* __restrict__ W0,
                                                  const float* __restrict__ X) {
    if (blockIdx.x < TRANS_BLOCKS) {
        int idx = blockIdx.x * 256 + threadIdx.x;   // covers II*HH = 89600 exactly
        int i = idx >> 7, h = idx & 127;
        g_W0T[idx] = W0[h * II + i];
        return;
    }
    int warp = ((blockIdx.x - TRANS_BLOCKS) * 256 + threadIdx.x) >> 5;
    int lane = threadIdx.x & 31;
    if (warp >= NROWS) return;
    const float4* xr4 = (const float4*)(X + (size_t)warp * II);

    float4 v[6];
    #pragma unroll
    for (int k = 0; k < 6; k++) {
        v[k] = make_float4(0.f, 0.f, 0.f, 0.f);
        if (k < 5 || lane < 15)
            v[k] = __ldg(xr4 + k * 32 + lane);
    }

    unsigned mw = 0;
    int myk = lane >> 2;
    int myg = lane & 3;
    #pragma unroll
    for (int k = 0; k < 6; k++) {
        unsigned nib = (v[k].x != 0.f ? 1u : 0u) | (v[k].y != 0.f ? 2u : 0u)
                     | (v[k].z != 0.f ? 4u : 0u) | (v[k].w != 0.f ? 8u : 0u);
        unsigned part = nib << ((lane & 7) * 4);
        part |= __shfl_xor_sync(0xffffffffu, part, 1);
        part |= __shfl_xor_sync(0xffffffffu, part, 2);
        part |= __shfl_xor_sync(0xffffffffu, part, 4);
        unsigned wd = __shfl_sync(0xffffffffu, part, myg * 8);
        if (k == myk) mw = wd;
    }
    if (lane < MW) g_masks[(size_t)warp * MW + lane] = mw;
}

// ---------------------------------------------------------------------------
// K1 (launch 1): SINGLE-PASS U gather, register accumulators, scalar decode
// (input spikes ~10% dense -> sparse iteration is right here).
// ---------------------------------------------------------------------------
__global__ void __launch_bounds__(256, 2) k_gather() {
    extern __shared__ float4 Ws4[];            // [192][32] float4
    int warp = threadIdx.x >> 5, lane = threadIdx.x & 31;
    int gw = blockIdx.x * 8 + warp;
    int r0 = gw * GW_ROWS;

    unsigned mw[GW_ROWS];
    #pragma unroll
    for (int k = 0; k < GW_ROWS; k++) {
        int row = r0 + k;
        mw[k] = (row < NROWS && lane < MW)
              ? g_masks[(size_t)row * MW + lane] : 0u;
    }

    float4 acc[GW_ROWS];
    #pragma unroll
    for (int k = 0; k < GW_ROWS; k++)
        acc[k] = make_float4(0.f, 0.f, 0.f, 0.f);

    for (int c = 0; c < NCHUNK; c++) {
        __syncthreads();
        for (int idx = threadIdx.x; idx < CHUNK_I * 32; idx += 256) {
            int i = idx >> 5, q = idx & 31;
            int gi = c * CHUNK_I + i;
            float4 v = make_float4(0.f, 0.f, 0.f, 0.f);
            if (gi < II) v = *(const float4*)(g_W0T + gi * HH + q * 4);
            Ws4[idx] = v;
        }
        __syncthreads();

        #pragma unroll
        for (int k = 0; k < GW_ROWS; k++) {
            #pragma unroll
            for (int w = 0; w < CHUNK_W; w++) {
                unsigned m = __shfl_sync(0xffffffffu, mw[k], c * CHUNK_W + w);
                const float4* p = Ws4 + w * 32 * 32 + lane;
                while (m) {
                    int j = __ffs(m) - 1;
                    m &= m - 1;
                    float4 v = p[j * 32];
                    acc[k].x += v.x; acc[k].y += v.y;
                    acc[k].z += v.z; acc[k].w += v.w;
                }
            }
        }
    }

    #pragma unroll
    for (int k = 0; k < GW_ROWS; k++) {
        int row = r0 + k;
        if (row < NROWS)
            ((float4*)(g_U + (size_t)row * HH))[lane] = acc[k];
    }
}

// ---------------------------------------------------------------------------
// K2 (launch 2): FUSED layer-0 scan + G gather (k0 spikes sparse -> ffs).
// ---------------------------------------------------------------------------
__global__ void __launch_bounds__(256, 2) k_layer0G(const float* __restrict__ W1) {
    extern __shared__ float sm2[];
    float* W1s = sm2;                               // [128][128]  64 KB
    unsigned* k0m = (unsigned*)(W1s + HH * HH);     // [2][TT][4]  3.2 KB

    for (int idx = threadIdx.x; idx < HH * HH; idx += 256) {
        int h = idx >> 7, j = idx & 127;
        W1s[j * 128 + h] = W1[idx];
    }
    __syncthreads();

    int w = threadIdx.x >> 5;
    int lane = threadIdx.x & 31;

    // ---- Phase A: LIF scan (prefetch depth 4) ----
    {
        int s = w >> 2, c = w & 3;                  // sample-in-CTA, chunk
        int b = blockIdx.x * 2 + s;
        const float* Ub = g_U + (size_t)b * TT * HH + c * 32 + lane;
        unsigned* K0s = k0m + s * TT * 4 + c;

        float s0 = 0.f, m0 = 0.f;
        float buf[4];
        #pragma unroll
        for (int r = 0; r < 4; r++) buf[r] = Ub[(size_t)r * HH];

        for (int t0 = 0; t0 < TT; t0 += 4) {
            float nxt[4];
            #pragma unroll
            for (int r = 0; r < 4; r++) {
                int tn = t0 + 4 + r;
                nxt[r] = (tn < TT) ? Ub[(size_t)tn * HH] : 0.f;
            }
            #pragma unroll
            for (int r = 0; r < 4; r++) {
                s0 = ALPHA * s0 + buf[r];
                m0 = BETA * m0 + s0;
                bool sp = m0 > 1.0f;
                if (sp) m0 = 0.f;
                unsigned bm = __ballot_sync(0xffffffffu, sp);
                if (lane == 0) K0s[(t0 + r) * 4] = bm;
            }
            #pragma unroll
            for (int r = 0; r < 4; r++) buf[r] = nxt[r];
        }
    }
    __syncthreads();

    // ---- Phase B: G gather (2*TT rows per CTA, warp per row) ----
    const float4* W1s4 = (const float4*)W1s;        // [j][32] float4
    for (int r = w; r < 2 * TT; r += 8) {
        int s2 = (r >= TT) ? 1 : 0;
        int t = r - s2 * TT;
        int b2 = blockIdx.x * 2 + s2;
        unsigned mw = (lane < 4) ? k0m[s2 * TT * 4 + t * 4 + lane] : 0u;
        float4 acc = make_float4(0.f, 0.f, 0.f, 0.f);
        #pragma unroll
        for (int q = 0; q < 4; q++) {
            unsigned m = __shfl_sync(0xffffffffu, mw, q);
            const float4* p = W1s4 + q * 32 * 32 + lane;
            while (m) {
                int j = __ffs(m) - 1;
                m &= m - 1;
                float4 v = p[j * 32];
                acc.x += v.x; acc.y += v.y; acc.z += v.z; acc.w += v.w;
            }
        }
        *(float4*)(g_G + ((size_t)b2 * TT + t) * HH + lane * 4) = acc;
    }
}

// ---------------------------------------------------------------------------
// K3 (launch 3 — profiled): layer-1 recurrence, WARP-PER-SAMPLE with DENSE
// PREDICATED float4 V-gather. Thread owns neurons {lane, lane+32, +64, +96};
// spike masks live in ballot results (registers) -> ZERO barriers, zero mask
// store/reload in the serial loop. Per j: 1 LDS.128 + 1 bit-test + 4
// predicated FADDs (component r accumulates V1^T[j][r*32+lane] ascending j
// -> per-neuron float addition sequence bit-identical to R12).
// 4 samples/CTA (128 thr), grid 128, ~81 KB SMEM, 1 CTA/SM.
// ---------------------------------------------------------------------------
__global__ void __launch_bounds__(128, 1) k_layer1(
    const float* __restrict__ V1, const float* __restrict__ Wr,
    const float* __restrict__ br, float* __restrict__ out)
{
    extern __shared__ float sm6[];
    float4* V1s4 = (float4*)sm6;                    // [128 j][32 lane] 64 KB
    float*  Wrs  = (float*)(V1s4 + HH * 32);        // 128*20  (10 KB)
    float*  brs  = Wrs + HH * OO;                   // 32
    uint4*  hist = (uint4*)(brs + 32);              // [4 warps][100] 6.4 KB

    // V1s4[j][ln] = {V1^T[j][ln], V1^T[j][ln+32], V1^T[j][ln+64], V1^T[j][ln+96]}
    //             = {V1[ln][j],   V1[ln+32][j],   V1[ln+64][j],   V1[ln+96][j]}
    for (int idx = threadIdx.x; idx < HH * 32; idx += 128) {
        int j = idx >> 5, ln = idx & 31;
        float4 v;
        v.x = V1[(ln      ) * HH + j];
        v.y = V1[(ln + 32 ) * HH + j];
        v.z = V1[(ln + 64 ) * HH + j];
        v.w = V1[(ln + 96 ) * HH + j];
        V1s4[idx] = v;
    }
    for (int idx = threadIdx.x; idx < OO * HH; idx += 128) {
        int o = idx >> 7, j = idx & 127;
        Wrs[j * OO + o] = Wr[idx];
    }
    if (threadIdx.x < OO) brs[threadIdx.x] = br[threadIdx.x];
    __syncthreads();

    int warp = threadIdx.x >> 5, lane = threadIdx.x & 31;
    int b = blockIdx.x * 4 + warp;
    uint4* hw = hist + warp * TT;

    const float* Gb = g_G + (size_t)b * TT * HH;
    float* outb = out + (size_t)b * TT * OO;
    const float4* Vp = V1s4 + lane;                 // source j at Vp[j*32]

    float s1[4] = {0,0,0,0}, m1[4] = {0,0,0,0};
    unsigned p0 = 0, p1 = 0, p2 = 0, p3 = 0;
    float gv[4], gn1[4];
    #pragma unroll
    for (int r = 0; r < 4; r++) gv[r]  = Gb[r * 32 + lane];
    #pragma unroll
    for (int r = 0; r < 4; r++) gn1[r] = Gb[HH + r * 32 + lane];

    for (int t = 0; t < TT; t++) {
        float gn2[4];
        #pragma unroll
        for (int r = 0; r < 4; r++)
            gn2[r] = (t + 2 < TT) ? Gb[(size_t)(t + 2) * HH + r * 32 + lane] : 0.f;

        // Dense predicated gather over prev-step k1 masks (warp-uniform).
        float a0 = 0.f, a1 = 0.f, a2 = 0.f, a3 = 0.f;
        #pragma unroll
        for (int jj = 0; jj < 32; jj++) {
            float4 v = Vp[jj * 32];
            if (p0 & (1u << jj)) { a0 += v.x; a1 += v.y; a2 += v.z; a3 += v.w; }
        }
        #pragma unroll
        for (int jj = 0; jj < 32; jj++) {
            float4 v = Vp[(32 + jj) * 32];
            if (p1 & (1u << jj)) { a0 += v.x; a1 += v.y; a2 += v.z; a3 += v.w; }
        }
        #pragma unroll
        for (int jj = 0; jj < 32; jj++) {
            float4 v = Vp[(64 + jj) * 32];
            if (p2 & (1u << jj)) { a0 += v.x; a1 += v.y; a2 += v.z; a3 += v.w; }
        }
        #pragma unroll
        for (int jj = 0; jj < 32; jj++) {
            float4 v = Vp[(96 + jj) * 32];
            if (p3 & (1u << jj)) { a0 += v.x; a1 += v.y; a2 += v.z; a3 += v.w; }
        }

        float ar[4] = {a0, a1, a2, a3};
        unsigned np[4];
        #pragma unroll
        for (int r = 0; r < 4; r++) {
            s1[r] = (ALPHA * s1[r] + gv[r]) + ar[r];
            m1[r] = BETA * m1[r] + s1[r];
            bool sp = m1[r] > 1.0f;
            if (sp) m1[r] = 0.f;
            np[r] = __ballot_sync(0xffffffffu, sp);
        }
        p0 = np[0]; p1 = np[1]; p2 = np[2]; p3 = np[3];
        if (lane == 0) hw[t] = make_uint4(p0, p1, p2, p3);
        #pragma unroll
        for (int r = 0; r < 4; r++) { gv[r] = gn1[r]; gn1[r] = gn2[r]; }
    }
    __syncwarp();

    // Post-loop: lane o (<20) does readout gather (ascending j, sparse) +
    // leaky scan for its channel — identical arithmetic order to R12.
    if (lane < OO) {
        const float C = 1.0f - LAM;
        float brv = brs[lane];
        float rp = 0.f;
        for (int t = 0; t < TT; t++) {
            uint4 ms = hw[t];
            float racc = brv;
            unsigned m;
            m = ms.x; while (m) { int j = __ffs(m) - 1; m &= m - 1; racc += Wrs[j * OO + lane]; }
            m = ms.y; while (m) { int j = __ffs(m) - 1; m &= m - 1; racc += Wrs[(32 + j) * OO + lane]; }
            m = ms.z; while (m) { int j = __ffs(m) - 1; m &= m - 1; racc += Wrs[(64 + j) * OO + lane]; }
            m = ms.w; while (m) { int j = __ffs(m) - 1; m &= m - 1; racc += Wrs[(96 + j) * OO + lane]; }
            rp = LAM * rp + C * racc;
            outb[(size_t)t * OO + lane] = rp;
        }
    }
}

// ---------------------------------------------------------------------------
// Launch
// ---------------------------------------------------------------------------
extern "C" void kernel_launch(void* const* d_in, const int* in_sizes, int n_in,
                              void* d_out, int out_size) {
    (void)in_sizes; (void)n_in; (void)out_size;
    const float* X  = (const float*)d_in[0];
    const float* W0 = (const float*)d_in[1];
    const float* W1 = (const float*)d_in[2];
    const float* V1 = (const float*)d_in[3];
    const float* Wr = (const float*)d_in[4];
    const float* br = (const float*)d_in[5];
    float* out = (float*)d_out;

    k_fused_tm<<<TRANS_BLOCKS + (NROWS + 7) / 8, 256>>>(W0, X);

    const size_t smem_g = (size_t)CHUNK_I * 32 * sizeof(float4);  // 98,304 B
    cudaFuncSetAttribute(k_gather, cudaFuncAttributeMaxDynamicSharedMemorySize,
                         (int)smem_g);
    int n_gw = (NROWS + GW_ROWS - 1) / GW_ROWS;
    k_gather<<<(n_gw + 7) / 8, 256, smem_g>>>();

    const size_t smem_0g = (size_t)HH * HH * sizeof(float)
                         + (size_t)2 * TT * 4 * sizeof(unsigned); // ~67.3 KB
    cudaFuncSetAttribute(k_layer0G, cudaFuncAttributeMaxDynamicSharedMemorySize,
                         (int)smem_0g);
    k_layer0G<<<BB / 2, 256, smem_0g>>>(W1);

    const size_t smem_l1 = (size_t)HH * 32 * sizeof(float4)       // V1s4 64 KB
                         + (size_t)(HH * OO + 32) * sizeof(float) // Wrs + brs
                         + (size_t)4 * TT * sizeof(uint4);        // hist 6.4 KB
    cudaFuncSetAttribute(k_layer1, cudaFuncAttributeMaxDynamicSharedMemorySize,
                         (int)smem_l1);
    k_layer1<<<BB / 4, 128, smem_l1>>>(V1, Wr, br, out);
}